// round 2
// baseline (speedup 1.0000x reference)
#include <cuda_runtime.h>
#include <cstdint>

// Correctly-rounded fp32 reciprocals of (1 + m/8), m = 0..7 (e4m3 mantissas).
static __constant__ float c_rcp_mant[8] = {
    1.0f,
    (float)(1.0 / 1.125),
    (float)(1.0 / 1.25),
    (float)(1.0 / 1.375),
    (float)(1.0 / 1.5),
    (float)(1.0 / 1.625),
    (float)(1.0 / 1.75),
    (float)(1.0 / 1.875),
};

// Markstein correctly-rounded division: rb must be RN(1/b). 3 FMA-class ops.
__device__ __forceinline__ float div_rn_(float a, float b, float rb) {
    float q0 = a * rb;
    float e  = fmaf(-q0, b, a);
    return fmaf(e, rb, q0);
}

// 4 threads cooperate on one 16-element group; each thread owns one float4.
// Global float4 index == global thread index -> perfectly coalesced LDG/STG.128.
__global__ __launch_bounds__(256)
void actquant_nvfp4_kernel(const float4* __restrict__ in,
                           float4* __restrict__ out,
                           int nvec) {
    const float GMF = (float)(1.0 / 6.0);  // 0x3E2AAAAB
    const float RGM = 6.0f;                // RN(1/GMF) == 6.0 exactly

    int t = blockIdx.x * blockDim.x + threadIdx.x;
    if (t >= nvec) return;

    float4 v = __ldcs(in + t);

    float x[4] = {v.x, v.y, v.z, v.w};

    // Per-thread partial amax over 4 elements.
    float amax = fmaxf(fmaxf(fabsf(x[0]), fabsf(x[1])),
                       fmaxf(fabsf(x[2]), fabsf(x[3])));
    // Butterfly reduce across the lane-quad (4 threads = 1 group).
    amax = fmaxf(amax, __shfl_xor_sync(0xFFFFFFFFu, amax, 1));
    amax = fmaxf(amax, __shfl_xor_sync(0xFFFFFFFFu, amax, 2));

    // scale_raw = (amax / gm) / 6, both IEEE-RN divisions (bit-exact).
    float d1   = div_rn_(amax, GMF, RGM);
    float sraw = div_rn_(d1, 6.0f, GMF);

    // Round to e4m3 grid: keep top-3 mantissa bits, round-half-DOWN
    // (matches reference argmin first-index tie-break), clamp to [2^-7, 480].
    unsigned sb  = __float_as_uint(sraw);
    unsigned rem = sb & 0xFFFFFu;
    unsigned res = (sb & ~0xFFFFFu) + ((rem > 0x80000u) ? 0x100000u : 0u);
    res = (res < 0x3C000000u) ? 0x3C000000u : res;  // 2^-7
    res = (res > 0x43F00000u) ? 0x43F00000u : res;  // 480
    float scale = __uint_as_float(res);

    // Correctly-rounded 1/scale: table reciprocal of mantissa, exact 2^-E.
    unsigned mm = (res >> 20) & 7u;
    int      E  = (int)((res >> 23) & 0xFFu) - 127;
    float    rs = __uint_as_float(__float_as_uint(c_rcp_mant[mm]) -
                                  (unsigned)(E << 23));

    float y[4];
#pragma unroll
    for (int i = 0; i < 4; i++) {
        // u = fp32div(fp32div(x, gm), scale), bit-exact (Markstein).
        float tq = div_rn_(x[i], GMF, RGM);
        float u  = div_rn_(tq, scale, rs);
        float a  = fabsf(u);

        // E2M1 bucket map == reference fp16-bit algorithm.
        // Thresholds are fp16-RNE midpoints; all round INTO the bucket (>=).
        float q;
        q = (a >= 0.24993896484375f) ? 0.5f : 0.0f;
        q = (a >= 0.749755859375f)   ? 1.0f : q;
        q = (a >= 1.24951171875f)    ? 1.5f : q;
        q = (a >= 1.74951171875f)    ? 2.0f : q;
        q = (a >= 2.4990234375f)     ? 3.0f : q;
        q = (a >= 3.4990234375f)     ? 4.0f : q;
        q = (a >= 4.998046875f)      ? 6.0f : q;

        // out = RN(RN(scale * q) * gm), sign from u.
        float o = __fmul_rn(__fmul_rn(scale, q), GMF);
        y[i] = __uint_as_float(__float_as_uint(o) |
                               (__float_as_uint(u) & 0x80000000u));
    }

    float4 w;
    w.x = y[0]; w.y = y[1]; w.z = y[2]; w.w = y[3];
    __stcs(out + t, w);
}

extern "C" void kernel_launch(void* const* d_in, const int* in_sizes, int n_in,
                              void* d_out, int out_size) {
    const float4* in  = (const float4*)d_in[0];
    float4*       out = (float4*)d_out;
    int n = in_sizes[0];
    int nvec = n / 4;                 // one float4 per thread, 4 threads/group
    int threads = 256;
    int blocks  = (nvec + threads - 1) / threads;
    actquant_nvfp4_kernel<<<blocks, threads>>>(in, out, nvec);
}

// round 3
// speedup vs baseline: 1.1616x; 1.1616x over previous
#include <cuda_runtime.h>
#include <cstdint>

__device__ __forceinline__ float rcp_approx_(float x) {
    float r;
    asm("rcp.approx.f32 %0, %1;" : "=f"(r) : "f"(x));
    return r;
}

// 4 threads per 16-element group (one float4 each, perfectly coalesced).
// Each thread processes 4 groups' worth of float4 (grid-stride), loads
// front-batched for MLP=4.
__global__ __launch_bounds__(256)
void actquant_nvfp4_kernel(const float4* __restrict__ in,
                           float4* __restrict__ out,
                           int nvec) {
    const float GMF = 0.16666667163372039794921875f;   // fp32(1/6) = 0x3E2AAAAB
    // C = RN( 1 / (6 * GMF) ), computed in double at compile time.
    const float C = (float)(1.0 / (6.0 * (double)0.16666667163372039794921875));

    const int t = blockIdx.x * blockDim.x + threadIdx.x;
    const int S = gridDim.x * blockDim.x;

    float4 v[4];
    bool ok[4];
#pragma unroll
    for (int k = 0; k < 4; k++) {
        int idx = t + k * S;
        ok[k] = (idx < nvec);
        v[k] = make_float4(0.f, 0.f, 0.f, 0.f);
        if (ok[k]) v[k] = in[idx];
    }

#pragma unroll
    for (int k = 0; k < 4; k++) {
        float x0 = v[k].x, x1 = v[k].y, x2 = v[k].z, x3 = v[k].w;

        // Group amax: per-thread partial + 2-level butterfly over the lane quad.
        float ax = fmaxf(fmaxf(fabsf(x0), fabsf(x1)),
                         fmaxf(fabsf(x2), fabsf(x3)));
        ax = fmaxf(ax, __shfl_xor_sync(0xFFFFFFFFu, ax, 1));
        ax = fmaxf(ax, __shfl_xor_sync(0xFFFFFFFFu, ax, 2));

        // sraw = (amax / gm) / 6  ~=  amax * C   (<=1 ulp difference)
        float sraw = ax * C;

        // Round to e4m3 grid: keep top-3 mantissa bits, round-half-DOWN
        // (reference argmin first-index tie-break), clamp to [2^-7, 480].
        unsigned sb  = __float_as_uint(sraw);
        unsigned res = (sb & 0xFFF00000u) +
                       (((sb & 0xFFFFFu) > 0x80000u) ? 0x100000u : 0u);
        res = (res < 0x3C000000u) ? 0x3C000000u : res;  // 2^-7
        res = (res > 0x43F00000u) ? 0x43F00000u : res;  // 480
        float scale = __uint_as_float(res);

        // R ~= 1/(gm*scale) = 6/scale (rcp.approx good to ~1 ulp).
        float R = 6.0f * rcp_approx_(scale);

        float y[4];
        float xs[4] = {x0, x1, x2, x3};
#pragma unroll
        for (int i = 0; i < 4; i++) {
            float u = xs[i] * R;
            float a = fminf(fabsf(u), 6.0f);

            // E2M1 bucket map for a >= ~0.75: after fp16-RNE pre-rounding,
            // every bucket boundary sits exactly 0x1000 below the fp32 E2M1
            // midpoint -> single add+mask in bit space (round-half-up).
            unsigned qb = (__float_as_uint(a) + 0x00201000u) & 0xFFC00000u;
            float q = fmaxf(__uint_as_float(qb), 1.0f);
            // Sub-1 buckets (E2M1 has 0.5 but not 0.75):
            q = (a < 0.749755859375f)   ? 0.5f : q;
            q = (a < 0.24993896484375f) ? 0.0f : q;

            // out = RN(RN(scale*q) * gm), sign from u (== sign of x).
            float o = __fmul_rn(__fmul_rn(scale, q), GMF);
            y[i] = __uint_as_float(__float_as_uint(o) |
                                   (__float_as_uint(u) & 0x80000000u));
        }

        if (ok[k]) {
            float4 w;
            w.x = y[0]; w.y = y[1]; w.z = y[2]; w.w = y[3];
            out[t + k * S] = w;
        }
    }
}

extern "C" void kernel_launch(void* const* d_in, const int* in_sizes, int n_in,
                              void* d_out, int out_size) {
    const float4* in  = (const float4*)d_in[0];
    float4*       out = (float4*)d_out;
    int n = in_sizes[0];
    int nvec = n / 4;               // one float4 = quarter group
    int threads = 256;
    int vec_per_thread = 4;
    int blocks = (nvec + threads * vec_per_thread - 1) / (threads * vec_per_thread);
    actquant_nvfp4_kernel<<<blocks, threads>>>(in, out, nvec);
}

// round 5
// speedup vs baseline: 1.2778x; 1.1000x over previous
#include <cuda_runtime.h>
#include <cstdint>

__device__ __forceinline__ float rcp_approx_(float x) {
    float r;
    asm("rcp.approx.f32 %0, %1;" : "=f"(r) : "f"(x));
    return r;
}

#define GMF_D 0.16666667163372039794921875  /* fp32(1/6) = 0x3E2AAAAB, as double */

// Core: one float4 (quarter of a 16-elem group). Lane quads own whole groups.
__device__ __forceinline__ float4 quant_f4_(float4 v) {
    const float C   = (float)(1.0 / (6.0 * GMF_D));   // RN(1/(6*gm))
    const float GMH = (float)(GMF_D * 0.5);           // gm/2, exact halving

    // Group amax: per-thread partial + 2-level butterfly over the lane quad.
    float ax = fmaxf(fmaxf(fabsf(v.x), fabsf(v.y)),
                     fmaxf(fabsf(v.z), fabsf(v.w)));
    ax = fmaxf(ax, __shfl_xor_sync(0xFFFFFFFFu, ax, 1));
    ax = fmaxf(ax, __shfl_xor_sync(0xFFFFFFFFu, ax, 2));

    // sraw = (amax/gm)/6 ~= amax * C (<=1 ulp).
    float sraw = ax * C;

    // e4m3 rounding: keep top-3 mantissa bits, round-half-DOWN
    // ((low20 > 0x80000) <=> (low20 + 0x7FFFF) carries), clamp [2^-7, 480].
    unsigned res = (__float_as_uint(sraw) + 0x7FFFFu) & 0xFFF00000u;
    res = max(res, 0x3C000000u);   // 2^-7
    res = min(res, 0x43F00000u);   // 480
    float scale = __uint_as_float(res);

    // Doubled domain: u' = 2 * x/(gm*scale) = x * (12*rcp(scale)).
    // RN commutes with *2, so u' == 2u exactly; thresholds double exactly.
    float R2  = 12.0f * rcp_approx_(scale);
    float sg2 = scale * GMH;   // out = q' * (scale*gm/2), q' = doubled bucket

    float xs[4] = {v.x, v.y, v.z, v.w};
    float ys[4];
#pragma unroll
    for (int i = 0; i < 4; i++) {
        float u = xs[i] * R2;
        float a = fabsf(u);

        // Bit-round valid only where doubled-E2M1 == 1-mantissa-bit grid:
        // binades [2,4)={2,3}, [4,8)={4,6}, [8,16)={8,12}. Clamp to [2,12].
        // (Boundaries 2.4990234375 / 3.4990234375 / 4.998046875 /
        //  6.998046875 / 9.99609375 land exactly on the +0x00201000 carry.)
        float a2 = fminf(fmaxf(a, 2.0f), 12.0f);
        unsigned qb = (__float_as_uint(a2) + 0x00201000u) & 0xFFC00000u;
        float q = __uint_as_float(qb);

        // Linear low buckets {0,1,2}: doubled thresholds (exact binary).
        q = (a >= 1.49951171875f)   ? q : 1.0f;
        q = (a >= 0.4998779296875f) ? q : 0.0f;

        // Sign from u (one LOP3), then single output multiply.
        float qs = __uint_as_float(__float_as_uint(q) |
                                   (__float_as_uint(u) & 0x80000000u));
        ys[i] = qs * sg2;
    }
    return make_float4(ys[0], ys[1], ys[2], ys[3]);
}

__global__ __launch_bounds__(256)
void actquant_nvfp4_kernel(const float4* __restrict__ in,
                           float4* __restrict__ out,
                           int nvec) {
    const int t = blockIdx.x * blockDim.x + threadIdx.x;
    const int S = gridDim.x * blockDim.x;

    if (t + 3 * S < nvec) {
        // Fast path: front-batched loads (MLP=4), perfectly coalesced.
        float4 v0 = in[t];
        float4 v1 = in[t + S];
        float4 v2 = in[t + 2 * S];
        float4 v3 = in[t + 3 * S];
        out[t]         = quant_f4_(v0);
        out[t + S]     = quant_f4_(v1);
        out[t + 2 * S] = quant_f4_(v2);
        out[t + 3 * S] = quant_f4_(v3);
    } else {
#pragma unroll
        for (int k = 0; k < 4; k++) {
            int idx = t + k * S;
            // Whole lane quads pass/fail together (nvec % 4 == 0 since
            // GROUP=16), so shuffles inside see live partners.
            if (idx < nvec) out[idx] = quant_f4_(in[idx]);
        }
    }
}

extern "C" void kernel_launch(void* const* d_in, const int* in_sizes, int n_in,
                              void* d_out, int out_size) {
    const float4* in  = (const float4*)d_in[0];
    float4*       out = (float4*)d_out;
    int n = in_sizes[0];
    int nvec = n / 4;               // one float4 = quarter group
    int threads = 256;
    int vec_per_thread = 4;
    int blocks = (nvec + threads * vec_per_thread - 1) / (threads * vec_per_thread);
    actquant_nvfp4_kernel<<<blocks, threads>>>(in, out, nvec);
}